// round 1
// baseline (speedup 1.0000x reference)
#include <cuda_runtime.h>

#define BB 4
#define NN 2048
#define DD 1024
#define EE 24
#define HH 8
#define HDD 128
#define RR (BB*NN)       // 8192 rows
#define ENTN (RR*HH)     // 65536 (row, head) entries
#define SWITCHLOSS 0.1f
#define ZLOSS 0.001f

// ---------------- scratch (static device globals; no runtime alloc) ----------------
__device__ int   g_topi[ENTN];
__device__ float g_gates[ENTN];
__device__ int   g_cnt[EE];
__device__ int   g_off[EE];
__device__ int   g_fill[EE];
__device__ int   g_perm[ENTN];
__device__ float g_q[(size_t)ENTN*HDD];    // (row*8+h)*128 + d
__device__ float g_k[(size_t)RR*HDD];
__device__ float g_v[(size_t)RR*HDD];
__device__ float g_o[(size_t)ENTN*HDD];    // attention out, (row*8+h)*128 + d
__device__ float g_yh[(size_t)ENTN*DD];    // per-entry projected output (268MB)
__device__ float g_pmean[EE];
__device__ float g_zsum;

// ---------------- init ----------------
__global__ void init_kernel() {
    int t = threadIdx.x;
    if (t < EE) { g_cnt[t] = 0; g_fill[t] = 0; g_pmean[t] = 0.f; }
    if (t == 0) g_zsum = 0.f;
}

// ---------------- gating: logits, softmax, top-8, aux accumulators ----------------
__global__ void gating_kernel(const float* __restrict__ x,
                              const int*   __restrict__ task_bh,
                              const float* __restrict__ Wg) {
    __shared__ float s_pm[EE];
    __shared__ int   s_ct[EE];
    __shared__ float s_z;
    int tid = threadIdx.x;
    if (tid < EE) { s_pm[tid] = 0.f; s_ct[tid] = 0; }
    if (tid == 0) s_z = 0.f;
    __syncthreads();

    int warp = tid >> 5, lane = tid & 31;
    int row = blockIdx.x * 8 + warp;     // 256 threads = 8 warps, warp per row
    if (row < RR) {
        int b = row / NN;
        const float* wg = Wg + (size_t)task_bh[b] * DD * EE;
        const float* xr = x + (size_t)row * DD;
        float acc[EE];
        #pragma unroll
        for (int e = 0; e < EE; e++) acc[e] = 0.f;
        for (int d = lane; d < DD; d += 32) {
            float xv = xr[d];
            const float* w = wg + d * EE;
            #pragma unroll
            for (int e = 0; e < EE; e++) acc[e] += xv * w[e];
        }
        #pragma unroll
        for (int e = 0; e < EE; e++) {
            float v = acc[e];
            #pragma unroll
            for (int o = 16; o > 0; o >>= 1) v += __shfl_down_sync(0xffffffffu, v, o);
            acc[e] = v;
        }
        if (lane == 0) {
            float m = -1e30f;
            #pragma unroll
            for (int e = 0; e < EE; e++) m = fmaxf(m, acc[e]);
            float p[EE]; float s = 0.f;
            #pragma unroll
            for (int e = 0; e < EE; e++) { p[e] = __expf(acc[e] - m); s += p[e]; }
            float lse = m + logf(s);
            atomicAdd(&s_z, lse * lse);
            float inv = 1.f / s;
            #pragma unroll
            for (int e = 0; e < EE; e++) atomicAdd(&s_pm[e], p[e] * inv);
            // top-8 (lowest index wins ties, matching jax.lax.top_k)
            bool used[EE];
            #pragma unroll
            for (int e = 0; e < EE; e++) used[e] = false;
            int   idxs[HH]; float vals[HH]; float sel = 0.f;
            for (int h = 0; h < HH; h++) {
                int bi = -1; float bv = -1.f;
                for (int e = 0; e < EE; e++)
                    if (!used[e] && p[e] > bv) { bv = p[e]; bi = e; }
                used[bi] = true; idxs[h] = bi; vals[h] = bv; sel += bv;
                atomicAdd(&s_ct[bi], 1);
            }
            float isel = 1.f / sel;
            #pragma unroll
            for (int h = 0; h < HH; h++) {
                g_topi[row * HH + h]  = idxs[h];
                g_gates[row * HH + h] = vals[h] * isel;
            }
        }
    }
    __syncthreads();
    if (tid < EE) { atomicAdd(&g_pmean[tid], s_pm[tid]); atomicAdd(&g_cnt[tid], s_ct[tid]); }
    if (tid == 0) atomicAdd(&g_zsum, s_z);
}

// ---------------- scan + scatter (build per-expert permutation) ----------------
__global__ void scan_kernel() {
    int s = 0;
    for (int e = 0; e < EE; e++) { g_off[e] = s; s += g_cnt[e]; }
}

__global__ void scatter_kernel() {
    int ent = blockIdx.x * 256 + threadIdx.x;
    if (ent < ENTN) {
        int e = g_topi[ent];
        int pos = g_off[e] + atomicAdd(&g_fill[e], 1);
        g_perm[pos] = ent;
    }
}

// ---------------- kv = x @ Wkv + bkv  (M=8192, N=256, K=1024) ----------------
__global__ void kv_gemm(const float* __restrict__ x,
                        const float* __restrict__ Wkv,
                        const float* __restrict__ bkv) {
    __shared__ __align__(16) float As[8][128];
    __shared__ __align__(16) float Bs[8][128];
    int tid = threadIdx.x;
    int m0 = blockIdx.x * 128, n0 = blockIdx.y * 128;
    int tr = tid / 16, tc = tid % 16;
    float acc[8][8];
    #pragma unroll
    for (int i = 0; i < 8; i++)
        #pragma unroll
        for (int j = 0; j < 8; j++) acc[i][j] = 0.f;

    for (int k0 = 0; k0 < DD; k0 += 8) {
        {
            int r = tid >> 1; int kk = (tid & 1) * 4;
            float4 av = *(const float4*)(x + (size_t)(m0 + r) * DD + k0 + kk);
            As[kk + 0][r] = av.x; As[kk + 1][r] = av.y; As[kk + 2][r] = av.z; As[kk + 3][r] = av.w;
        }
        {
            int kr = tid >> 5; int cc = (tid & 31) * 4;
            *(float4*)&Bs[kr][cc] = *(const float4*)(Wkv + (size_t)(k0 + kr) * 256 + n0 + cc);
        }
        __syncthreads();
        #pragma unroll
        for (int k = 0; k < 8; k++) {
            float4 a0 = *(float4*)&As[k][tr * 8], a1 = *(float4*)&As[k][tr * 8 + 4];
            float4 b0 = *(float4*)&Bs[k][tc * 8], b1 = *(float4*)&Bs[k][tc * 8 + 4];
            float a[8] = {a0.x, a0.y, a0.z, a0.w, a1.x, a1.y, a1.z, a1.w};
            float bb[8] = {b0.x, b0.y, b0.z, b0.w, b1.x, b1.y, b1.z, b1.w};
            #pragma unroll
            for (int i = 0; i < 8; i++)
                #pragma unroll
                for (int j = 0; j < 8; j++) acc[i][j] += a[i] * bb[j];
        }
        __syncthreads();
    }
    #pragma unroll
    for (int i = 0; i < 8; i++) {
        int row = m0 + tr * 8 + i;
        #pragma unroll
        for (int j = 0; j < 8; j++) {
            int col = n0 + tc * 8 + j;
            float vv = acc[i][j] + bkv[col];
            if (col < HDD) g_k[(size_t)row * HDD + col] = vv;
            else           g_v[(size_t)row * HDD + col - HDD] = vv;
        }
    }
}

// ---------------- grouped Q projection: per expert, gathered rows ----------------
// q[ent] = x[ent>>3] @ Wq[e]     (M=cnt[e], N=128, K=1024)
__global__ void q_gemm(const float* __restrict__ x, const float* __restrict__ Wq) {
    int e = blockIdx.x;
    int cnt = g_cnt[e];
    int m0 = blockIdx.y * 128;
    if (m0 >= cnt) return;
    __shared__ __align__(16) float As[8][128];
    __shared__ __align__(16) float Bs[8][128];
    __shared__ int s_ent[128];
    int tid = threadIdx.x;
    int off = g_off[e];
    if (tid < 128) s_ent[tid] = (m0 + tid < cnt) ? g_perm[off + m0 + tid] : -1;
    __syncthreads();
    int tr = tid / 16, tc = tid % 16;
    float acc[8][8];
    #pragma unroll
    for (int i = 0; i < 8; i++)
        #pragma unroll
        for (int j = 0; j < 8; j++) acc[i][j] = 0.f;
    const float* Wb = Wq + (size_t)e * DD * HDD;

    for (int k0 = 0; k0 < DD; k0 += 8) {
        {
            int r = tid >> 1; int kk = (tid & 1) * 4;
            int ent = s_ent[r];
            float4 av = make_float4(0.f, 0.f, 0.f, 0.f);
            if (ent >= 0) av = *(const float4*)(x + (size_t)(ent >> 3) * DD + k0 + kk);
            As[kk + 0][r] = av.x; As[kk + 1][r] = av.y; As[kk + 2][r] = av.z; As[kk + 3][r] = av.w;
        }
        {
            int kr = tid >> 5; int cc = (tid & 31) * 4;
            *(float4*)&Bs[kr][cc] = *(const float4*)(Wb + (size_t)(k0 + kr) * HDD + cc);
        }
        __syncthreads();
        #pragma unroll
        for (int k = 0; k < 8; k++) {
            float4 a0 = *(float4*)&As[k][tr * 8], a1 = *(float4*)&As[k][tr * 8 + 4];
            float4 b0 = *(float4*)&Bs[k][tc * 8], b1 = *(float4*)&Bs[k][tc * 8 + 4];
            float a[8] = {a0.x, a0.y, a0.z, a0.w, a1.x, a1.y, a1.z, a1.w};
            float bb[8] = {b0.x, b0.y, b0.z, b0.w, b1.x, b1.y, b1.z, b1.w};
            #pragma unroll
            for (int i = 0; i < 8; i++)
                #pragma unroll
                for (int j = 0; j < 8; j++) acc[i][j] += a[i] * bb[j];
        }
        __syncthreads();
    }
    #pragma unroll
    for (int i = 0; i < 8; i++) {
        int ent = s_ent[tr * 8 + i];
        if (ent >= 0) {
            #pragma unroll
            for (int j = 0; j < 8; j++)
                g_q[(size_t)ent * HDD + tc * 8 + j] = acc[i][j];
        }
    }
}

// ---------------- flash attention: per (b, h, q-tile of 64) ----------------
#define QS_STRIDE 132
#define PS_STRIDE 68
#define ATTN_SMEM ((64*QS_STRIDE*3 + 64*PS_STRIDE + 3*64) * (int)sizeof(float))

__global__ void attn_kernel() {
    extern __shared__ __align__(16) float sm[];
    float* Qs  = sm;                        // [64][132]
    float* Ks  = Qs + 64 * QS_STRIDE;       // [64][132]
    float* Vs  = Ks + 64 * QS_STRIDE;       // [64][132]
    float* Ps  = Vs + 64 * QS_STRIDE;       // [64][68]
    float* s_m = Ps + 64 * PS_STRIDE;
    float* s_l = s_m + 64;
    float* s_al = s_l + 64;

    int tid = threadIdx.x;                  // 256 threads
    int b = blockIdx.z, h = blockIdx.y;
    int q0 = blockIdx.x * 64;
    int rowbase = b * NN + q0;
    const float scale = 0.08838834764831845f;  // HD^-0.5

    // load Q tile (transpose not needed; rows padded to 132)
    for (int i = tid; i < 64 * 32; i += 256) {
        int r = i >> 5; int c = (i & 31) * 4;
        *(float4*)&Qs[r * QS_STRIDE + c] =
            *(const float4*)&g_q[((size_t)(rowbase + r) * HH + h) * HDD + c];
    }
    if (tid < 64) { s_m[tid] = -1e30f; s_l[tid] = 0.f; }
    __syncthreads();

    int tr = tid / 16, tc = tid % 16;
    float acc[4][8];
    #pragma unroll
    for (int i = 0; i < 4; i++)
        #pragma unroll
        for (int j = 0; j < 8; j++) acc[i][j] = 0.f;

    for (int kv0 = 0; kv0 < NN; kv0 += 64) {
        // load K, V tiles
        for (int i = tid; i < 64 * 32; i += 256) {
            int r = i >> 5; int c = (i & 31) * 4;
            *(float4*)&Ks[r * QS_STRIDE + c] = *(const float4*)&g_k[(size_t)(b * NN + kv0 + r) * HDD + c];
            *(float4*)&Vs[r * QS_STRIDE + c] = *(const float4*)&g_v[(size_t)(b * NN + kv0 + r) * HDD + c];
        }
        __syncthreads();

        // S = Q K^T (64x64, K=128), per-thread 4x4
        float sacc[4][4];
        #pragma unroll
        for (int i = 0; i < 4; i++)
            #pragma unroll
            for (int j = 0; j < 4; j++) sacc[i][j] = 0.f;
        for (int k = 0; k < 128; k += 4) {
            float4 a[4], bq[4];
            #pragma unroll
            for (int i = 0; i < 4; i++) a[i]  = *(float4*)&Qs[(tr * 4 + i) * QS_STRIDE + k];
            #pragma unroll
            for (int j = 0; j < 4; j++) bq[j] = *(float4*)&Ks[(tc * 4 + j) * QS_STRIDE + k];
            #pragma unroll
            for (int i = 0; i < 4; i++)
                #pragma unroll
                for (int j = 0; j < 4; j++)
                    sacc[i][j] += a[i].x * bq[j].x + a[i].y * bq[j].y
                                + a[i].z * bq[j].z + a[i].w * bq[j].w;
        }
        #pragma unroll
        for (int i = 0; i < 4; i++) {
            float4 st = make_float4(sacc[i][0] * scale, sacc[i][1] * scale,
                                    sacc[i][2] * scale, sacc[i][3] * scale);
            *(float4*)&Ps[(tr * 4 + i) * PS_STRIDE + tc * 4] = st;
        }
        __syncthreads();

        // row-wise online softmax update (threads 0..63, one row each)
        if (tid < 64) {
            float rmax = -1e30f;
            for (int k = 0; k < 64; k++) rmax = fmaxf(rmax, Ps[tid * PS_STRIDE + k]);
            float mold = s_m[tid];
            float mnew = fmaxf(mold, rmax);
            float alpha = __expf(mold - mnew);
            float rs = 0.f;
            for (int k = 0; k < 64; k++) {
                float p = __expf(Ps[tid * PS_STRIDE + k] - mnew);
                Ps[tid * PS_STRIDE + k] = p;
                rs += p;
            }
            s_l[tid] = s_l[tid] * alpha + rs;
            s_m[tid] = mnew;
            s_al[tid] = alpha;
        }
        __syncthreads();

        // O = O*alpha + P@V  (64x128, K=64)
        float al[4];
        #pragma unroll
        for (int i = 0; i < 4; i++) al[i] = s_al[tr * 4 + i];
        #pragma unroll
        for (int i = 0; i < 4; i++)
            #pragma unroll
            for (int j = 0; j < 8; j++) acc[i][j] *= al[i];

        for (int k = 0; k < 64; k++) {
            float a[4];
            #pragma unroll
            for (int i = 0; i < 4; i++) a[i] = Ps[(tr * 4 + i) * PS_STRIDE + k];
            float4 b0 = *(float4*)&Vs[k * QS_STRIDE + tc * 8];
            float4 b1 = *(float4*)&Vs[k * QS_STRIDE + tc * 8 + 4];
            float bb[8] = {b0.x, b0.y, b0.z, b0.w, b1.x, b1.y, b1.z, b1.w};
            #pragma unroll
            for (int i = 0; i < 4; i++)
                #pragma unroll
                for (int j = 0; j < 8; j++) acc[i][j] += a[i] * bb[j];
        }
        __syncthreads();
    }

    // finalize and store
    float il[4];
    #pragma unroll
    for (int i = 0; i < 4; i++) il[i] = 1.f / s_l[tr * 4 + i];
    #pragma unroll
    for (int i = 0; i < 4; i++) {
        int m = tr * 4 + i;
        #pragma unroll
        for (int j = 0; j < 8; j++)
            g_o[((size_t)(rowbase + m) * HH + h) * HDD + tc * 8 + j] = acc[i][j] * il[i];
    }
}

// ---------------- grouped output projection: yh[ent] = gate * (o[ent] @ Wo[e]) ----------------
// per expert: M=cnt[e], N=1024, K=128
__global__ void yh_gemm(const float* __restrict__ Wo) {
    int e = blockIdx.x;
    int cnt = g_cnt[e];
    int m0 = blockIdx.y * 128;
    if (m0 >= cnt) return;
    int n0 = blockIdx.z * 128;
    __shared__ __align__(16) float As[8][128];
    __shared__ __align__(16) float Bs[8][128];
    __shared__ int   s_ent[128];
    __shared__ float s_gate[128];
    int tid = threadIdx.x;
    int off = g_off[e];
    if (tid < 128) {
        int ent = (m0 + tid < cnt) ? g_perm[off + m0 + tid] : -1;
        s_ent[tid] = ent;
        s_gate[tid] = (ent >= 0) ? g_gates[ent] : 0.f;
    }
    __syncthreads();
    int tr = tid / 16, tc = tid % 16;
    float acc[8][8];
    #pragma unroll
    for (int i = 0; i < 8; i++)
        #pragma unroll
        for (int j = 0; j < 8; j++) acc[i][j] = 0.f;
    const float* Wb = Wo + (size_t)e * HDD * DD;

    for (int k0 = 0; k0 < HDD; k0 += 8) {
        {
            int r = tid >> 1; int kk = (tid & 1) * 4;
            int ent = s_ent[r];
            float4 av = make_float4(0.f, 0.f, 0.f, 0.f);
            if (ent >= 0) av = *(const float4*)&g_o[(size_t)ent * HDD + k0 + kk];
            As[kk + 0][r] = av.x; As[kk + 1][r] = av.y; As[kk + 2][r] = av.z; As[kk + 3][r] = av.w;
        }
        {
            int kr = tid >> 5; int cc = (tid & 31) * 4;
            *(float4*)&Bs[kr][cc] = *(const float4*)(Wb + (size_t)(k0 + kr) * DD + n0 + cc);
        }
        __syncthreads();
        #pragma unroll
        for (int k = 0; k < 8; k++) {
            float4 a0 = *(float4*)&As[k][tr * 8], a1 = *(float4*)&As[k][tr * 8 + 4];
            float4 b0 = *(float4*)&Bs[k][tc * 8], b1 = *(float4*)&Bs[k][tc * 8 + 4];
            float a[8] = {a0.x, a0.y, a0.z, a0.w, a1.x, a1.y, a1.z, a1.w};
            float bb[8] = {b0.x, b0.y, b0.z, b0.w, b1.x, b1.y, b1.z, b1.w};
            #pragma unroll
            for (int i = 0; i < 8; i++)
                #pragma unroll
                for (int j = 0; j < 8; j++) acc[i][j] += a[i] * bb[j];
        }
        __syncthreads();
    }
    #pragma unroll
    for (int i = 0; i < 8; i++) {
        int mi = tr * 8 + i;
        int ent = s_ent[mi];
        if (ent >= 0) {
            float g = s_gate[mi];
            #pragma unroll
            for (int j = 0; j < 8; j++)
                g_yh[(size_t)ent * DD + n0 + tc * 8 + j] = acc[i][j] * g;
        }
    }
}

// ---------------- reduce over heads: y[row][c] = sum_h yh[row*8+h][c] ----------------
__global__ void reduce_kernel(float* __restrict__ out) {
    int idx = blockIdx.x * 256 + threadIdx.x;
    if (idx < RR * DD) {
        int row = idx >> 10;
        int c = idx & 1023;
        float s = 0.f;
        #pragma unroll
        for (int h = 0; h < HH; h++)
            s += g_yh[(size_t)(row * HH + h) * DD + c];
        out[idx] = s;
    }
}

// ---------------- aux loss ----------------
__global__ void aux_kernel(float* __restrict__ out) {
    float sw = 0.f;
    for (int e = 0; e < EE; e++)
        sw += ((float)g_cnt[e] / (float)RR) * (g_pmean[e] / (float)RR);
    float aux = SWITCHLOSS * (float)EE * sw + ZLOSS * (g_zsum / (float)RR);
    out[(size_t)RR * DD] = aux;
}

// ---------------- launch ----------------
extern "C" void kernel_launch(void* const* d_in, const int* in_sizes, int n_in,
                              void* d_out, int out_size) {
    const float* x       = (const float*)d_in[0];
    const int*   task_bh = (const int*)  d_in[1];
    const float* Wg      = (const float*)d_in[2];
    const float* Wq      = (const float*)d_in[3];
    const float* Wo      = (const float*)d_in[4];
    const float* Wkv     = (const float*)d_in[5];
    const float* bkv     = (const float*)d_in[6];
    float* out = (float*)d_out;

    cudaFuncSetAttribute(attn_kernel, cudaFuncAttributeMaxDynamicSharedMemorySize, ATTN_SMEM);

    init_kernel<<<1, 64>>>();
    gating_kernel<<<RR / 8, 256>>>(x, task_bh, Wg);
    scan_kernel<<<1, 1>>>();
    scatter_kernel<<<ENTN / 256, 256>>>();
    kv_gemm<<<dim3(RR / 128, 2), 256>>>(x, Wkv, bkv);
    q_gemm<<<dim3(EE, ENTN / 128), 256>>>(x, Wq);
    attn_kernel<<<dim3(NN / 64, HH, BB), 256, ATTN_SMEM>>>();
    yh_gemm<<<dim3(EE, ENTN / 128, DD / 128), 256>>>(Wo);
    reduce_kernel<<<(RR * DD) / 256, 256>>>(out);
    aux_kernel<<<1, 1>>>(out);
}

// round 3
// speedup vs baseline: 2.7676x; 2.7676x over previous
#include <cuda_runtime.h>
#include <cstdint>

#define BB 4
#define NN 2048
#define DD 1024
#define EE 24
#define HH 8
#define HDD 128
#define RR (BB*NN)       // 8192 rows
#define ENTN (RR*HH)     // 65536 (row, head) entries
#define SWITCHLOSS 0.1f
#define ZLOSS 0.001f

// ---------------- scratch (static device globals; no runtime alloc) ----------------
__device__ int   g_topi[ENTN];
__device__ float g_gates[ENTN];
__device__ int   g_cnt[EE];
__device__ int   g_off[EE];
__device__ int   g_fill[EE];
__device__ int   g_perm[ENTN];
__device__ float g_q[(size_t)ENTN*HDD];
__device__ float g_k[(size_t)RR*HDD];
__device__ float g_v[(size_t)RR*HDD];
__device__ float g_o[(size_t)ENTN*HDD];
__device__ float g_yh[(size_t)ENTN*DD];
__device__ float g_pmean[EE];
__device__ float g_zsum;

// ---------------- tf32 mma helpers ----------------
__device__ __forceinline__ float to_tf32(float x) {
    uint32_t r; asm("cvt.rna.tf32.f32 %0, %1;" : "=r"(r) : "f"(x));
    return __uint_as_float(r);
}
__device__ __forceinline__ void mma8(float* c, const uint32_t* a, const uint32_t* b) {
    asm volatile(
        "mma.sync.aligned.m16n8k8.row.col.f32.tf32.tf32.f32 "
        "{%0,%1,%2,%3},{%4,%5,%6,%7},{%8,%9},{%0,%1,%2,%3};\n"
        : "+f"(c[0]), "+f"(c[1]), "+f"(c[2]), "+f"(c[3])
        : "r"(a[0]), "r"(a[1]), "r"(a[2]), "r"(a[3]), "r"(b[0]), "r"(b[1]));
}
__device__ __forceinline__ uint32_t fu(float x) { return __float_as_uint(x); }

// ---------------- init ----------------
__global__ void init_kernel() {
    int t = threadIdx.x;
    if (t < EE) { g_cnt[t] = 0; g_fill[t] = 0; g_pmean[t] = 0.f; }
    if (t == 0) g_zsum = 0.f;
}

// ---------------- gating (exact fp32 so top-k matches reference) ----------------
__global__ void gating_kernel(const float* __restrict__ x,
                              const int*   __restrict__ task_bh,
                              const float* __restrict__ Wg) {
    __shared__ float s_pm[EE];
    __shared__ int   s_ct[EE];
    __shared__ float s_z;
    int tid = threadIdx.x;
    if (tid < EE) { s_pm[tid] = 0.f; s_ct[tid] = 0; }
    if (tid == 0) s_z = 0.f;
    __syncthreads();

    int warp = tid >> 5, lane = tid & 31;
    int row = blockIdx.x * 8 + warp;
    if (row < RR) {
        int b = row / NN;
        const float* wg = Wg + (size_t)task_bh[b] * DD * EE;
        const float* xr = x + (size_t)row * DD;
        float acc[EE];
        #pragma unroll
        for (int e = 0; e < EE; e++) acc[e] = 0.f;
        for (int d = lane; d < DD; d += 32) {
            float xv = xr[d];
            const float* w = wg + d * EE;
            #pragma unroll
            for (int e = 0; e < EE; e++) acc[e] += xv * w[e];
        }
        #pragma unroll
        for (int e = 0; e < EE; e++) {
            float v = acc[e];
            #pragma unroll
            for (int o = 16; o > 0; o >>= 1) v += __shfl_down_sync(0xffffffffu, v, o);
            acc[e] = v;
        }
        if (lane == 0) {
            float m = -1e30f;
            #pragma unroll
            for (int e = 0; e < EE; e++) m = fmaxf(m, acc[e]);
            float p[EE]; float s = 0.f;
            #pragma unroll
            for (int e = 0; e < EE; e++) { p[e] = __expf(acc[e] - m); s += p[e]; }
            float lse = m + logf(s);
            atomicAdd(&s_z, lse * lse);
            float inv = 1.f / s;
            #pragma unroll
            for (int e = 0; e < EE; e++) atomicAdd(&s_pm[e], p[e] * inv);
            bool used[EE];
            #pragma unroll
            for (int e = 0; e < EE; e++) used[e] = false;
            int   idxs[HH]; float vals[HH]; float sel = 0.f;
            for (int h = 0; h < HH; h++) {
                int bi = -1; float bv = -1.f;
                for (int e = 0; e < EE; e++)
                    if (!used[e] && p[e] > bv) { bv = p[e]; bi = e; }
                used[bi] = true; idxs[h] = bi; vals[h] = bv; sel += bv;
                atomicAdd(&s_ct[bi], 1);
            }
            float isel = 1.f / sel;
            #pragma unroll
            for (int h = 0; h < HH; h++) {
                g_topi[row * HH + h]  = idxs[h];
                g_gates[row * HH + h] = vals[h] * isel;
            }
        }
    }
    __syncthreads();
    if (tid < EE) { atomicAdd(&g_pmean[tid], s_pm[tid]); atomicAdd(&g_cnt[tid], s_ct[tid]); }
    if (tid == 0) atomicAdd(&g_zsum, s_z);
}

__global__ void scan_kernel() {
    int s = 0;
    for (int e = 0; e < EE; e++) { g_off[e] = s; s += g_cnt[e]; }
}

__global__ void scatter_kernel() {
    int ent = blockIdx.x * 256 + threadIdx.x;
    if (ent < ENTN) {
        int e = g_topi[ent];
        int pos = g_off[e] + atomicAdd(&g_fill[e], 1);
        g_perm[pos] = ent;
    }
}

// =================== tf32 tensor-core GEMMs ===================
// Tile: 128x128, 256 threads = 8 warps as 4(m) x 2(n); warp tile 32x64.
// A in smem row-major [128][20] (stride 20 -> conflict-free frag loads),
// B in smem k-major [16][136] (stride 136 -> conflict-free).

#define AST 20
#define BST 136

// ---------------- kv = x @ Wkv + bkv ----------------
__global__ __launch_bounds__(256, 1) void kv_gemm(const float* __restrict__ x,
                                                  const float* __restrict__ Wkv,
                                                  const float* __restrict__ bkv) {
    __shared__ float As[128][AST];
    __shared__ float Bs[16][BST];
    int tid = threadIdx.x;
    int m0 = blockIdx.x * 128, n0 = blockIdx.y * 128;
    int w = tid >> 5, lane = tid & 31, g = lane >> 2, tig = lane & 3;
    int wm = w & 3, wn = w >> 2;
    float c[2][8][4];
    #pragma unroll
    for (int i = 0; i < 2; i++) for (int j = 0; j < 8; j++) for (int q = 0; q < 4; q++) c[i][j][q] = 0.f;

    for (int k0 = 0; k0 < DD; k0 += 16) {
        #pragma unroll
        for (int i = 0; i < 2; i++) {
            int idx = tid * 2 + i; int r = idx >> 2, kq = (idx & 3) * 4;
            float4 v = *(const float4*)(x + (size_t)(m0 + r) * DD + k0 + kq);
            float4 t = make_float4(to_tf32(v.x), to_tf32(v.y), to_tf32(v.z), to_tf32(v.w));
            *(float4*)&As[r][kq] = t;
        }
        #pragma unroll
        for (int i = 0; i < 2; i++) {
            int idx = tid * 2 + i; int kr = idx >> 5, cc = (idx & 31) * 4;
            float4 v = *(const float4*)(Wkv + (size_t)(k0 + kr) * 256 + n0 + cc);
            float4 t = make_float4(to_tf32(v.x), to_tf32(v.y), to_tf32(v.z), to_tf32(v.w));
            *(float4*)&Bs[kr][cc] = t;
        }
        __syncthreads();
        #pragma unroll
        for (int ko = 0; ko < 16; ko += 8) {
            uint32_t a[2][4], bf[8][2];
            #pragma unroll
            for (int i = 0; i < 2; i++) {
                int rb = wm * 32 + i * 16;
                a[i][0] = fu(As[rb + g][ko + tig]);
                a[i][1] = fu(As[rb + g + 8][ko + tig]);
                a[i][2] = fu(As[rb + g][ko + tig + 4]);
                a[i][3] = fu(As[rb + g + 8][ko + tig + 4]);
            }
            #pragma unroll
            for (int j = 0; j < 8; j++) {
                int cb = wn * 64 + j * 8;
                bf[j][0] = fu(Bs[ko + tig][cb + g]);
                bf[j][1] = fu(Bs[ko + tig + 4][cb + g]);
            }
            #pragma unroll
            for (int i = 0; i < 2; i++)
                #pragma unroll
                for (int j = 0; j < 8; j++) mma8(c[i][j], a[i], bf[j]);
        }
        __syncthreads();
    }
    #pragma unroll
    for (int i = 0; i < 2; i++) {
        #pragma unroll
        for (int j = 0; j < 8; j++) {
            int col = n0 + wn * 64 + j * 8 + 2 * tig;
            #pragma unroll
            for (int half = 0; half < 2; half++) {
                int row = m0 + wm * 32 + i * 16 + g + half * 8;
                float v0 = c[i][j][half * 2 + 0] + bkv[col];
                float v1 = c[i][j][half * 2 + 1] + bkv[col + 1];
                float* dst = (col < HDD) ? &g_k[(size_t)row * HDD + col]
                                         : &g_v[(size_t)row * HDD + col - HDD];
                dst[0] = v0; dst[1] = v1;
            }
        }
    }
}

// ---------------- grouped q projection ----------------
__global__ __launch_bounds__(256, 1) void q_gemm(const float* __restrict__ x,
                                                 const float* __restrict__ Wq) {
    int e = blockIdx.x;
    int cnt = g_cnt[e];
    int m0 = blockIdx.y * 128;
    if (m0 >= cnt) return;
    __shared__ float As[128][AST];
    __shared__ float Bs[16][BST];
    __shared__ int s_ent[128];
    int tid = threadIdx.x;
    int off = g_off[e];
    if (tid < 128) s_ent[tid] = (m0 + tid < cnt) ? g_perm[off + m0 + tid] : -1;
    __syncthreads();
    int w = tid >> 5, lane = tid & 31, g = lane >> 2, tig = lane & 3;
    int wm = w & 3, wn = w >> 2;
    float c[2][8][4];
    #pragma unroll
    for (int i = 0; i < 2; i++) for (int j = 0; j < 8; j++) for (int q = 0; q < 4; q++) c[i][j][q] = 0.f;
    const float* Wb = Wq + (size_t)e * DD * HDD;

    for (int k0 = 0; k0 < DD; k0 += 16) {
        #pragma unroll
        for (int i = 0; i < 2; i++) {
            int idx = tid * 2 + i; int r = idx >> 2, kq = (idx & 3) * 4;
            int ent = s_ent[r];
            float4 v = make_float4(0.f, 0.f, 0.f, 0.f);
            if (ent >= 0) v = *(const float4*)(x + (size_t)(ent >> 3) * DD + k0 + kq);
            float4 t = make_float4(to_tf32(v.x), to_tf32(v.y), to_tf32(v.z), to_tf32(v.w));
            *(float4*)&As[r][kq] = t;
        }
        #pragma unroll
        for (int i = 0; i < 2; i++) {
            int idx = tid * 2 + i; int kr = idx >> 5, cc = (idx & 31) * 4;
            if (cc < HDD) {
                float4 v = *(const float4*)(Wb + (size_t)(k0 + kr) * HDD + cc);
                float4 t = make_float4(to_tf32(v.x), to_tf32(v.y), to_tf32(v.z), to_tf32(v.w));
                *(float4*)&Bs[kr][cc] = t;
            }
        }
        __syncthreads();
        #pragma unroll
        for (int ko = 0; ko < 16; ko += 8) {
            uint32_t a[2][4], bf[8][2];
            #pragma unroll
            for (int i = 0; i < 2; i++) {
                int rb = wm * 32 + i * 16;
                a[i][0] = fu(As[rb + g][ko + tig]);
                a[i][1] = fu(As[rb + g + 8][ko + tig]);
                a[i][2] = fu(As[rb + g][ko + tig + 4]);
                a[i][3] = fu(As[rb + g + 8][ko + tig + 4]);
            }
            #pragma unroll
            for (int j = 0; j < 8; j++) {
                int cb = wn * 64 + j * 8;
                bf[j][0] = fu(Bs[ko + tig][cb + g]);
                bf[j][1] = fu(Bs[ko + tig + 4][cb + g]);
            }
            #pragma unroll
            for (int i = 0; i < 2; i++)
                #pragma unroll
                for (int j = 0; j < 8; j++) mma8(c[i][j], a[i], bf[j]);
        }
        __syncthreads();
    }
    #pragma unroll
    for (int i = 0; i < 2; i++) {
        #pragma unroll
        for (int half = 0; half < 2; half++) {
            int mi = wm * 32 + i * 16 + g + half * 8;
            int ent = s_ent[mi];
            if (ent >= 0) {
                #pragma unroll
                for (int j = 0; j < 8; j++) {
                    int col = wn * 64 + j * 8 + 2 * tig;
                    g_q[(size_t)ent * HDD + col]     = c[i][j][half * 2 + 0];
                    g_q[(size_t)ent * HDD + col + 1] = c[i][j][half * 2 + 1];
                }
            }
        }
    }
}

// ---------------- flash attention (tf32 mma) ----------------
#define QST 132
#define KVST 136
#define PST 68
#define ATTN_SMEM ((128*QST + 2*64*KVST + 128*PST) * (int)sizeof(float))

__global__ __launch_bounds__(256, 1) void attn_kernel() {
    extern __shared__ float sm[];
    float (*Qs)[QST]  = (float(*)[QST])sm;
    float (*Ks)[KVST] = (float(*)[KVST])(sm + 128 * QST);
    float (*Vs)[KVST] = (float(*)[KVST])(sm + 128 * QST + 64 * KVST);
    float (*Ps)[PST]  = (float(*)[PST]) (sm + 128 * QST + 2 * 64 * KVST);

    int tid = threadIdx.x, w = tid >> 5, lane = tid & 31, g = lane >> 2, tig = lane & 3;
    int b = blockIdx.z, h = blockIdx.y, q0 = blockIdx.x * 128;
    const float scale = 0.08838834764831845f;

    #pragma unroll
    for (int i = 0; i < 16; i++) {
        int idx = tid + i * 256; int r = idx >> 5, cc = (idx & 31) * 4;
        float4 v = *(const float4*)&g_q[(((size_t)(b * NN + q0 + r)) * HH + h) * HDD + cc];
        float4 t = make_float4(to_tf32(v.x * scale), to_tf32(v.y * scale),
                               to_tf32(v.z * scale), to_tf32(v.w * scale));
        *(float4*)&Qs[r][cc] = t;
    }

    float oacc[16][4];
    #pragma unroll
    for (int j = 0; j < 16; j++) for (int q = 0; q < 4; q++) oacc[j][q] = 0.f;
    float m0 = -1e30f, m1 = -1e30f, l0 = 0.f, l1 = 0.f;

    for (int kv0 = 0; kv0 < NN; kv0 += 64) {
        __syncthreads();
        #pragma unroll
        for (int i = 0; i < 8; i++) {
            int idx = tid + i * 256; int r = idx >> 5, cc = (idx & 31) * 4;
            float4 kv = *(const float4*)&g_k[(size_t)(b * NN + kv0 + r) * HDD + cc];
            *(float4*)&Ks[r][cc] = make_float4(to_tf32(kv.x), to_tf32(kv.y), to_tf32(kv.z), to_tf32(kv.w));
            float4 vv = *(const float4*)&g_v[(size_t)(b * NN + kv0 + r) * HDD + cc];
            *(float4*)&Vs[r][cc] = make_float4(to_tf32(vv.x), to_tf32(vv.y), to_tf32(vv.z), to_tf32(vv.w));
        }
        __syncthreads();

        // S = Q K^T  (16 rows per warp x 64 kv)
        float s[8][4];
        #pragma unroll
        for (int j = 0; j < 8; j++) for (int q = 0; q < 4; q++) s[j][q] = 0.f;
        int rb = w * 16;
        #pragma unroll
        for (int ko = 0; ko < 128; ko += 8) {
            uint32_t a[4];
            a[0] = fu(Qs[rb + g][ko + tig]);
            a[1] = fu(Qs[rb + g + 8][ko + tig]);
            a[2] = fu(Qs[rb + g][ko + tig + 4]);
            a[3] = fu(Qs[rb + g + 8][ko + tig + 4]);
            #pragma unroll
            for (int j = 0; j < 8; j++) {
                uint32_t bf[2]; int cb = j * 8;
                bf[0] = fu(Ks[cb + g][ko + tig]);
                bf[1] = fu(Ks[cb + g][ko + tig + 4]);
                mma8(s[j], a, bf);
            }
        }

        // online softmax
        float mx0 = -1e30f, mx1 = -1e30f;
        #pragma unroll
        for (int j = 0; j < 8; j++) {
            mx0 = fmaxf(mx0, fmaxf(s[j][0], s[j][1]));
            mx1 = fmaxf(mx1, fmaxf(s[j][2], s[j][3]));
        }
        mx0 = fmaxf(mx0, __shfl_xor_sync(0xffffffffu, mx0, 1));
        mx0 = fmaxf(mx0, __shfl_xor_sync(0xffffffffu, mx0, 2));
        mx1 = fmaxf(mx1, __shfl_xor_sync(0xffffffffu, mx1, 1));
        mx1 = fmaxf(mx1, __shfl_xor_sync(0xffffffffu, mx1, 2));
        float mn0 = fmaxf(m0, mx0), mn1 = fmaxf(m1, mx1);
        float al0 = __expf(m0 - mn0), al1 = __expf(m1 - mn1);
        float rs0 = 0.f, rs1 = 0.f;
        #pragma unroll
        for (int j = 0; j < 8; j++) {
            float p00 = __expf(s[j][0] - mn0), p01 = __expf(s[j][1] - mn0);
            float p10 = __expf(s[j][2] - mn1), p11 = __expf(s[j][3] - mn1);
            rs0 += p00 + p01; rs1 += p10 + p11;
            int cb = j * 8 + 2 * tig;
            Ps[rb + g][cb] = to_tf32(p00); Ps[rb + g][cb + 1] = to_tf32(p01);
            Ps[rb + g + 8][cb] = to_tf32(p10); Ps[rb + g + 8][cb + 1] = to_tf32(p11);
        }
        rs0 += __shfl_xor_sync(0xffffffffu, rs0, 1);
        rs0 += __shfl_xor_sync(0xffffffffu, rs0, 2);
        rs1 += __shfl_xor_sync(0xffffffffu, rs1, 1);
        rs1 += __shfl_xor_sync(0xffffffffu, rs1, 2);
        l0 = l0 * al0 + rs0; l1 = l1 * al1 + rs1;
        m0 = mn0; m1 = mn1;
        #pragma unroll
        for (int j = 0; j < 16; j++) {
            oacc[j][0] *= al0; oacc[j][1] *= al0;
            oacc[j][2] *= al1; oacc[j][3] *= al1;
        }
        __syncwarp();

        // O += P V  (16 rows x 128 d, k=64)
        #pragma unroll
        for (int ko = 0; ko < 64; ko += 8) {
            uint32_t a[4];
            a[0] = fu(Ps[rb + g][ko + tig]);
            a[1] = fu(Ps[rb + g + 8][ko + tig]);
            a[2] = fu(Ps[rb + g][ko + tig + 4]);
            a[3] = fu(Ps[rb + g + 8][ko + tig + 4]);
            #pragma unroll
            for (int j = 0; j < 16; j++) {
                uint32_t bf[2]; int db = j * 8;
                bf[0] = fu(Vs[ko + tig][db + g]);
                bf[1] = fu(Vs[ko + tig + 4][db + g]);
                mma8(oacc[j], a, bf);
            }
        }
    }

    float inv0 = 1.f / l0, inv1 = 1.f / l1;
    int rowg0 = b * NN + q0 + w * 16 + g;
    #pragma unroll
    for (int j = 0; j < 16; j++) {
        int col = j * 8 + 2 * tig;
        float* d0 = &g_o[((size_t)rowg0 * HH + h) * HDD + col];
        d0[0] = oacc[j][0] * inv0; d0[1] = oacc[j][1] * inv0;
        float* d1 = &g_o[((size_t)(rowg0 + 8) * HH + h) * HDD + col];
        d1[0] = oacc[j][2] * inv1; d1[1] = oacc[j][3] * inv1;
    }
}

// ---------------- grouped output projection ----------------
__global__ __launch_bounds__(256, 1) void yh_gemm(const float* __restrict__ Wo) {
    int e = blockIdx.x;
    int cnt = g_cnt[e];
    int m0 = blockIdx.y * 128;
    if (m0 >= cnt) return;
    int n0 = blockIdx.z * 128;
    __shared__ float As[128][AST];
    __shared__ float Bs[16][BST];
    __shared__ int   s_ent[128];
    __shared__ float s_gate[128];
    int tid = threadIdx.x;
    int off = g_off[e];
    if (tid < 128) {
        int ent = (m0 + tid < cnt) ? g_perm[off + m0 + tid] : -1;
        s_ent[tid] = ent;
        s_gate[tid] = (ent >= 0) ? g_gates[ent] : 0.f;
    }
    __syncthreads();
    int w = tid >> 5, lane = tid & 31, g = lane >> 2, tig = lane & 3;
    int wm = w & 3, wn = w >> 2;
    float c[2][8][4];
    #pragma unroll
    for (int i = 0; i < 2; i++) for (int j = 0; j < 8; j++) for (int q = 0; q < 4; q++) c[i][j][q] = 0.f;
    const float* Wb = Wo + (size_t)e * HDD * DD;

    for (int k0 = 0; k0 < HDD; k0 += 16) {
        #pragma unroll
        for (int i = 0; i < 2; i++) {
            int idx = tid * 2 + i; int r = idx >> 2, kq = (idx & 3) * 4;
            int ent = s_ent[r];
            float4 v = make_float4(0.f, 0.f, 0.f, 0.f);
            if (ent >= 0) v = *(const float4*)&g_o[(size_t)ent * HDD + k0 + kq];
            *(float4*)&As[r][kq] = make_float4(to_tf32(v.x), to_tf32(v.y), to_tf32(v.z), to_tf32(v.w));
        }
        #pragma unroll
        for (int i = 0; i < 2; i++) {
            int idx = tid * 2 + i; int kr = idx >> 5, cc = (idx & 31) * 4;
            float4 v = *(const float4*)(Wb + (size_t)(k0 + kr) * DD + n0 + cc);
            *(float4*)&Bs[kr][cc] = make_float4(to_tf32(v.x), to_tf32(v.y), to_tf32(v.z), to_tf32(v.w));
        }
        __syncthreads();
        #pragma unroll
        for (int ko = 0; ko < 16; ko += 8) {
            uint32_t a[2][4], bf[8][2];
            #pragma unroll
            for (int i = 0; i < 2; i++) {
                int rb = wm * 32 + i * 16;
                a[i][0] = fu(As[rb + g][ko + tig]);
                a[i][1] = fu(As[rb + g + 8][ko + tig]);
                a[i][2] = fu(As[rb + g][ko + tig + 4]);
                a[i][3] = fu(As[rb + g + 8][ko + tig + 4]);
            }
            #pragma unroll
            for (int j = 0; j < 8; j++) {
                int cb = wn * 64 + j * 8;
                bf[j][0] = fu(Bs[ko + tig][cb + g]);
                bf[j][1] = fu(Bs[ko + tig + 4][cb + g]);
            }
            #pragma unroll
            for (int i = 0; i < 2; i++)
                #pragma unroll
                for (int j = 0; j < 8; j++) mma8(c[i][j], a[i], bf[j]);
        }
        __syncthreads();
    }
    #pragma unroll
    for (int i = 0; i < 2; i++) {
        #pragma unroll
        for (int half = 0; half < 2; half++) {
            int mi = wm * 32 + i * 16 + g + half * 8;
            int ent = s_ent[mi];
            if (ent >= 0) {
                float gt = s_gate[mi];
                #pragma unroll
                for (int j = 0; j < 8; j++) {
                    int col = n0 + wn * 64 + j * 8 + 2 * tig;
                    g_yh[(size_t)ent * DD + col]     = c[i][j][half * 2 + 0] * gt;
                    g_yh[(size_t)ent * DD + col + 1] = c[i][j][half * 2 + 1] * gt;
                }
            }
        }
    }
}

// ---------------- reduce over heads (vectorized) ----------------
__global__ void reduce_kernel(float4* __restrict__ out) {
    int idx = blockIdx.x * 256 + threadIdx.x;
    if (idx < RR * DD / 4) {
        int row = idx / (DD / 4);
        int c = idx % (DD / 4);
        const float4* yh4 = (const float4*)g_yh;
        float4 s = make_float4(0.f, 0.f, 0.f, 0.f);
        #pragma unroll
        for (int h = 0; h < HH; h++) {
            float4 v = yh4[(size_t)(row * HH + h) * (DD / 4) + c];
            s.x += v.x; s.y += v.y; s.z += v.z; s.w += v.w;
        }
        out[idx] = s;
    }
}

__global__ void aux_kernel(float* __restrict__ out) {
    float sw = 0.f;
    for (int e = 0; e < EE; e++)
        sw += ((float)g_cnt[e] / (float)RR) * (g_pmean[e] / (float)RR);
    float aux = SWITCHLOSS * (float)EE * sw + ZLOSS * (g_zsum / (float)RR);
    out[(size_t)RR * DD] = aux;
}

// ---------------- launch ----------------
extern "C" void kernel_launch(void* const* d_in, const int* in_sizes, int n_in,
                              void* d_out, int out_size) {
    const float* x       = (const float*)d_in[0];
    const int*   task_bh = (const int*)  d_in[1];
    const float* Wg      = (const float*)d_in[2];
    const float* Wq      = (const float*)d_in[3];
    const float* Wo      = (const float*)d_in[4];
    const float* Wkv     = (const float*)d_in[5];
    const float* bkv     = (const float*)d_in[6];
    float* out = (float*)d_out;

    cudaFuncSetAttribute(attn_kernel, cudaFuncAttributeMaxDynamicSharedMemorySize, ATTN_SMEM);

    init_kernel<<<1, 64>>>();
    gating_kernel<<<RR / 8, 256>>>(x, task_bh, Wg);
    scan_kernel<<<1, 1>>>();
    scatter_kernel<<<ENTN / 256, 256>>>();
    kv_gemm<<<dim3(RR / 128, 2), 256>>>(x, Wkv, bkv);
    q_gemm<<<dim3(EE, ENTN / 128), 256>>>(x, Wq);
    attn_kernel<<<dim3(NN / 128, HH, BB), 256, ATTN_SMEM>>>();
    yh_gemm<<<dim3(EE, ENTN / 128, DD / 128), 256>>>(Wo);
    reduce_kernel<<<(RR * DD / 4) / 256, 256>>>((float4*)out);
    aux_kernel<<<1, 1>>>(out);
}

// round 4
// speedup vs baseline: 2.7708x; 1.0012x over previous
#include <cuda_runtime.h>
#include <cstdint>

#define BB 4
#define NN 2048
#define DD 1024
#define EE 24
#define HH 8
#define HDD 128
#define RR (BB*NN)       // 8192 rows
#define ENTN (RR*HH)     // 65536 (row, head) entries
#define SWITCHLOSS 0.1f
#define ZLOSS 0.001f

// ---------------- scratch (static device globals; no runtime alloc) ----------------
__device__ int   g_topi[ENTN];
__device__ float g_gates[ENTN];
__device__ int   g_cnt[EE];
__device__ int   g_off[EE];
__device__ int   g_fill[EE];
__device__ int   g_perm[ENTN];
__device__ float g_q[(size_t)ENTN*HDD];
__device__ float g_k[(size_t)RR*HDD];
__device__ float g_v[(size_t)RR*HDD];
__device__ float g_o[(size_t)ENTN*HDD];
__device__ float g_yh[(size_t)ENTN*DD];
__device__ float g_pmean[EE];
__device__ float g_zsum;

// ---------------- tf32 mma helpers ----------------
__device__ __forceinline__ float to_tf32(float x) {
    uint32_t r; asm("cvt.rna.tf32.f32 %0, %1;" : "=r"(r) : "f"(x));
    return __uint_as_float(r);
}
__device__ __forceinline__ void mma8(float* c, const uint32_t* a, const uint32_t* b) {
    asm volatile(
        "mma.sync.aligned.m16n8k8.row.col.f32.tf32.tf32.f32 "
        "{%0,%1,%2,%3},{%4,%5,%6,%7},{%8,%9},{%0,%1,%2,%3};\n"
        : "+f"(c[0]), "+f"(c[1]), "+f"(c[2]), "+f"(c[3])
        : "r"(a[0]), "r"(a[1]), "r"(a[2]), "r"(a[3]), "r"(b[0]), "r"(b[1]));
}
__device__ __forceinline__ uint32_t fu(float x) { return __float_as_uint(x); }

// ---------------- init ----------------
__global__ void init_kernel() {
    int t = threadIdx.x;
    if (t < EE) { g_cnt[t] = 0; g_fill[t] = 0; g_pmean[t] = 0.f; }
    if (t == 0) g_zsum = 0.f;
}

// ---------------- gating (exact fp32 so top-k matches reference) ----------------
__global__ void gating_kernel(const float* __restrict__ x,
                              const int*   __restrict__ task_bh,
                              const float* __restrict__ Wg) {
    __shared__ float s_pm[EE];
    __shared__ int   s_ct[EE];
    __shared__ float s_z;
    int tid = threadIdx.x;
    if (tid < EE) { s_pm[tid] = 0.f; s_ct[tid] = 0; }
    if (tid == 0) s_z = 0.f;
    __syncthreads();

    int warp = tid >> 5, lane = tid & 31;
    int row = blockIdx.x * 8 + warp;
    if (row < RR) {
        int b = row / NN;
        const float* wg = Wg + (size_t)task_bh[b] * DD * EE;
        const float* xr = x + (size_t)row * DD;
        float acc[EE];
        #pragma unroll
        for (int e = 0; e < EE; e++) acc[e] = 0.f;
        for (int d = lane; d < DD; d += 32) {
            float xv = xr[d];
            const float* w = wg + d * EE;
            #pragma unroll
            for (int e = 0; e < EE; e++) acc[e] += xv * w[e];
        }
        #pragma unroll
        for (int e = 0; e < EE; e++) {
            float v = acc[e];
            #pragma unroll
            for (int o = 16; o > 0; o >>= 1) v += __shfl_down_sync(0xffffffffu, v, o);
            acc[e] = v;
        }
        if (lane == 0) {
            float m = -1e30f;
            #pragma unroll
            for (int e = 0; e < EE; e++) m = fmaxf(m, acc[e]);
            float p[EE]; float s = 0.f;
            #pragma unroll
            for (int e = 0; e < EE; e++) { p[e] = __expf(acc[e] - m); s += p[e]; }
            float lse = m + logf(s);
            atomicAdd(&s_z, lse * lse);
            float inv = 1.f / s;
            #pragma unroll
            for (int e = 0; e < EE; e++) atomicAdd(&s_pm[e], p[e] * inv);
            bool used[EE];
            #pragma unroll
            for (int e = 0; e < EE; e++) used[e] = false;
            int   idxs[HH]; float vals[HH]; float sel = 0.f;
            for (int h = 0; h < HH; h++) {
                int bi = -1; float bv = -1.f;
                for (int e = 0; e < EE; e++)
                    if (!used[e] && p[e] > bv) { bv = p[e]; bi = e; }
                used[bi] = true; idxs[h] = bi; vals[h] = bv; sel += bv;
                atomicAdd(&s_ct[bi], 1);
            }
            float isel = 1.f / sel;
            #pragma unroll
            for (int h = 0; h < HH; h++) {
                g_topi[row * HH + h]  = idxs[h];
                g_gates[row * HH + h] = vals[h] * isel;
            }
        }
    }
    __syncthreads();
    if (tid < EE) { atomicAdd(&g_pmean[tid], s_pm[tid]); atomicAdd(&g_cnt[tid], s_ct[tid]); }
    if (tid == 0) atomicAdd(&g_zsum, s_z);
}

__global__ void scan_kernel() {
    int s = 0;
    for (int e = 0; e < EE; e++) { g_off[e] = s; s += g_cnt[e]; }
}

__global__ void scatter_kernel() {
    int ent = blockIdx.x * 256 + threadIdx.x;
    if (ent < ENTN) {
        int e = g_topi[ent];
        int pos = g_off[e] + atomicAdd(&g_fill[e], 1);
        g_perm[pos] = ent;
    }
}

// =================== tf32 tensor-core GEMMs ===================
// Tile: 128x128, 256 threads = 8 warps as 4(m) x 2(n); warp tile 32x64.
// A in smem row-major [128][20] (stride 20 -> conflict-free frag loads),
// B in smem k-major [16][136] (stride 136 -> conflict-free).

#define AST 20
#define BST 136

// ---------------- kv = x @ Wkv + bkv ----------------
__global__ __launch_bounds__(256, 1) void kv_gemm(const float* __restrict__ x,
                                                  const float* __restrict__ Wkv,
                                                  const float* __restrict__ bkv) {
    __shared__ float As[128][AST];
    __shared__ float Bs[16][BST];
    int tid = threadIdx.x;
    int m0 = blockIdx.x * 128, n0 = blockIdx.y * 128;
    int w = tid >> 5, lane = tid & 31, g = lane >> 2, tig = lane & 3;
    int wm = w & 3, wn = w >> 2;
    float c[2][8][4];
    #pragma unroll
    for (int i = 0; i < 2; i++) for (int j = 0; j < 8; j++) for (int q = 0; q < 4; q++) c[i][j][q] = 0.f;

    for (int k0 = 0; k0 < DD; k0 += 16) {
        #pragma unroll
        for (int i = 0; i < 2; i++) {
            int idx = tid * 2 + i; int r = idx >> 2, kq = (idx & 3) * 4;
            float4 v = *(const float4*)(x + (size_t)(m0 + r) * DD + k0 + kq);
            float4 t = make_float4(to_tf32(v.x), to_tf32(v.y), to_tf32(v.z), to_tf32(v.w));
            *(float4*)&As[r][kq] = t;
        }
        #pragma unroll
        for (int i = 0; i < 2; i++) {
            int idx = tid * 2 + i; int kr = idx >> 5, cc = (idx & 31) * 4;
            float4 v = *(const float4*)(Wkv + (size_t)(k0 + kr) * 256 + n0 + cc);
            float4 t = make_float4(to_tf32(v.x), to_tf32(v.y), to_tf32(v.z), to_tf32(v.w));
            *(float4*)&Bs[kr][cc] = t;
        }
        __syncthreads();
        #pragma unroll
        for (int ko = 0; ko < 16; ko += 8) {
            uint32_t a[2][4], bf[8][2];
            #pragma unroll
            for (int i = 0; i < 2; i++) {
                int rb = wm * 32 + i * 16;
                a[i][0] = fu(As[rb + g][ko + tig]);
                a[i][1] = fu(As[rb + g + 8][ko + tig]);
                a[i][2] = fu(As[rb + g][ko + tig + 4]);
                a[i][3] = fu(As[rb + g + 8][ko + tig + 4]);
            }
            #pragma unroll
            for (int j = 0; j < 8; j++) {
                int cb = wn * 64 + j * 8;
                bf[j][0] = fu(Bs[ko + tig][cb + g]);
                bf[j][1] = fu(Bs[ko + tig + 4][cb + g]);
            }
            #pragma unroll
            for (int i = 0; i < 2; i++)
                #pragma unroll
                for (int j = 0; j < 8; j++) mma8(c[i][j], a[i], bf[j]);
        }
        __syncthreads();
    }
    #pragma unroll
    for (int i = 0; i < 2; i++) {
        #pragma unroll
        for (int j = 0; j < 8; j++) {
            int col = n0 + wn * 64 + j * 8 + 2 * tig;
            #pragma unroll
            for (int half = 0; half < 2; half++) {
                int row = m0 + wm * 32 + i * 16 + g + half * 8;
                float v0 = c[i][j][half * 2 + 0] + bkv[col];
                float v1 = c[i][j][half * 2 + 1] + bkv[col + 1];
                float* dst = (col < HDD) ? &g_k[(size_t)row * HDD + col]
                                         : &g_v[(size_t)row * HDD + col - HDD];
                dst[0] = v0; dst[1] = v1;
            }
        }
    }
}

// ---------------- grouped q projection ----------------
__global__ __launch_bounds__(256, 1) void q_gemm(const float* __restrict__ x,
                                                 const float* __restrict__ Wq) {
    int e = blockIdx.x;
    int cnt = g_cnt[e];
    int m0 = blockIdx.y * 128;
    if (m0 >= cnt) return;
    __shared__ float As[128][AST];
    __shared__ float Bs[16][BST];
    __shared__ int s_ent[128];
    int tid = threadIdx.x;
    int off = g_off[e];
    if (tid < 128) s_ent[tid] = (m0 + tid < cnt) ? g_perm[off + m0 + tid] : -1;
    __syncthreads();
    int w = tid >> 5, lane = tid & 31, g = lane >> 2, tig = lane & 3;
    int wm = w & 3, wn = w >> 2;
    float c[2][8][4];
    #pragma unroll
    for (int i = 0; i < 2; i++) for (int j = 0; j < 8; j++) for (int q = 0; q < 4; q++) c[i][j][q] = 0.f;
    const float* Wb = Wq + (size_t)e * DD * HDD;

    for (int k0 = 0; k0 < DD; k0 += 16) {
        #pragma unroll
        for (int i = 0; i < 2; i++) {
            int idx = tid * 2 + i; int r = idx >> 2, kq = (idx & 3) * 4;
            int ent = s_ent[r];
            float4 v = make_float4(0.f, 0.f, 0.f, 0.f);
            if (ent >= 0) v = *(const float4*)(x + (size_t)(ent >> 3) * DD + k0 + kq);
            float4 t = make_float4(to_tf32(v.x), to_tf32(v.y), to_tf32(v.z), to_tf32(v.w));
            *(float4*)&As[r][kq] = t;
        }
        #pragma unroll
        for (int i = 0; i < 2; i++) {
            int idx = tid * 2 + i; int kr = idx >> 5, cc = (idx & 31) * 4;
            if (cc < HDD) {
                float4 v = *(const float4*)(Wb + (size_t)(k0 + kr) * HDD + cc);
                float4 t = make_float4(to_tf32(v.x), to_tf32(v.y), to_tf32(v.z), to_tf32(v.w));
                *(float4*)&Bs[kr][cc] = t;
            }
        }
        __syncthreads();
        #pragma unroll
        for (int ko = 0; ko < 16; ko += 8) {
            uint32_t a[2][4], bf[8][2];
            #pragma unroll
            for (int i = 0; i < 2; i++) {
                int rb = wm * 32 + i * 16;
                a[i][0] = fu(As[rb + g][ko + tig]);
                a[i][1] = fu(As[rb + g + 8][ko + tig]);
                a[i][2] = fu(As[rb + g][ko + tig + 4]);
                a[i][3] = fu(As[rb + g + 8][ko + tig + 4]);
            }
            #pragma unroll
            for (int j = 0; j < 8; j++) {
                int cb = wn * 64 + j * 8;
                bf[j][0] = fu(Bs[ko + tig][cb + g]);
                bf[j][1] = fu(Bs[ko + tig + 4][cb + g]);
            }
            #pragma unroll
            for (int i = 0; i < 2; i++)
                #pragma unroll
                for (int j = 0; j < 8; j++) mma8(c[i][j], a[i], bf[j]);
        }
        __syncthreads();
    }
    #pragma unroll
    for (int i = 0; i < 2; i++) {
        #pragma unroll
        for (int half = 0; half < 2; half++) {
            int mi = wm * 32 + i * 16 + g + half * 8;
            int ent = s_ent[mi];
            if (ent >= 0) {
                #pragma unroll
                for (int j = 0; j < 8; j++) {
                    int col = wn * 64 + j * 8 + 2 * tig;
                    g_q[(size_t)ent * HDD + col]     = c[i][j][half * 2 + 0];
                    g_q[(size_t)ent * HDD + col + 1] = c[i][j][half * 2 + 1];
                }
            }
        }
    }
}

// ---------------- flash attention (tf32 mma) ----------------
#define QST 132
#define KVST 136
#define PST 68
#define ATTN_SMEM ((128*QST + 2*64*KVST + 128*PST) * (int)sizeof(float))

__global__ __launch_bounds__(256, 1) void attn_kernel() {
    extern __shared__ float sm[];
    float (*Qs)[QST]  = (float(*)[QST])sm;
    float (*Ks)[KVST] = (float(*)[KVST])(sm + 128 * QST);
    float (*Vs)[KVST] = (float(*)[KVST])(sm + 128 * QST + 64 * KVST);
    float (*Ps)[PST]  = (float(*)[PST]) (sm + 128 * QST + 2 * 64 * KVST);

    int tid = threadIdx.x, w = tid >> 5, lane = tid & 31, g = lane >> 2, tig = lane & 3;
    int b = blockIdx.z, h = blockIdx.y, q0 = blockIdx.x * 128;
    const float scale = 0.08838834764831845f;

    #pragma unroll
    for (int i = 0; i < 16; i++) {
        int idx = tid + i * 256; int r = idx >> 5, cc = (idx & 31) * 4;
        float4 v = *(const float4*)&g_q[(((size_t)(b * NN + q0 + r)) * HH + h) * HDD + cc];
        float4 t = make_float4(to_tf32(v.x * scale), to_tf32(v.y * scale),
                               to_tf32(v.z * scale), to_tf32(v.w * scale));
        *(float4*)&Qs[r][cc] = t;
    }

    float oacc[16][4];
    #pragma unroll
    for (int j = 0; j < 16; j++) for (int q = 0; q < 4; q++) oacc[j][q] = 0.f;
    float m0 = -1e30f, m1 = -1e30f, l0 = 0.f, l1 = 0.f;

    for (int kv0 = 0; kv0 < NN; kv0 += 64) {
        __syncthreads();
        #pragma unroll
        for (int i = 0; i < 8; i++) {
            int idx = tid + i * 256; int r = idx >> 5, cc = (idx & 31) * 4;
            float4 kv = *(const float4*)&g_k[(size_t)(b * NN + kv0 + r) * HDD + cc];
            *(float4*)&Ks[r][cc] = make_float4(to_tf32(kv.x), to_tf32(kv.y), to_tf32(kv.z), to_tf32(kv.w));
            float4 vv = *(const float4*)&g_v[(size_t)(b * NN + kv0 + r) * HDD + cc];
            *(float4*)&Vs[r][cc] = make_float4(to_tf32(vv.x), to_tf32(vv.y), to_tf32(vv.z), to_tf32(vv.w));
        }
        __syncthreads();

        // S = Q K^T  (16 rows per warp x 64 kv)
        float s[8][4];
        #pragma unroll
        for (int j = 0; j < 8; j++) for (int q = 0; q < 4; q++) s[j][q] = 0.f;
        int rb = w * 16;
        #pragma unroll
        for (int ko = 0; ko < 128; ko += 8) {
            uint32_t a[4];
            a[0] = fu(Qs[rb + g][ko + tig]);
            a[1] = fu(Qs[rb + g + 8][ko + tig]);
            a[2] = fu(Qs[rb + g][ko + tig + 4]);
            a[3] = fu(Qs[rb + g + 8][ko + tig + 4]);
            #pragma unroll
            for (int j = 0; j < 8; j++) {
                uint32_t bf[2]; int cb = j * 8;
                bf[0] = fu(Ks[cb + g][ko + tig]);
                bf[1] = fu(Ks[cb + g][ko + tig + 4]);
                mma8(s[j], a, bf);
            }
        }

        // online softmax
        float mx0 = -1e30f, mx1 = -1e30f;
        #pragma unroll
        for (int j = 0; j < 8; j++) {
            mx0 = fmaxf(mx0, fmaxf(s[j][0], s[j][1]));
            mx1 = fmaxf(mx1, fmaxf(s[j][2], s[j][3]));
        }
        mx0 = fmaxf(mx0, __shfl_xor_sync(0xffffffffu, mx0, 1));
        mx0 = fmaxf(mx0, __shfl_xor_sync(0xffffffffu, mx0, 2));
        mx1 = fmaxf(mx1, __shfl_xor_sync(0xffffffffu, mx1, 1));
        mx1 = fmaxf(mx1, __shfl_xor_sync(0xffffffffu, mx1, 2));
        float mn0 = fmaxf(m0, mx0), mn1 = fmaxf(m1, mx1);
        float al0 = __expf(m0 - mn0), al1 = __expf(m1 - mn1);
        float rs0 = 0.f, rs1 = 0.f;
        #pragma unroll
        for (int j = 0; j < 8; j++) {
            float p00 = __expf(s[j][0] - mn0), p01 = __expf(s[j][1] - mn0);
            float p10 = __expf(s[j][2] - mn1), p11 = __expf(s[j][3] - mn1);
            rs0 += p00 + p01; rs1 += p10 + p11;
            int cb = j * 8 + 2 * tig;
            Ps[rb + g][cb] = to_tf32(p00); Ps[rb + g][cb + 1] = to_tf32(p01);
            Ps[rb + g + 8][cb] = to_tf32(p10); Ps[rb + g + 8][cb + 1] = to_tf32(p11);
        }
        rs0 += __shfl_xor_sync(0xffffffffu, rs0, 1);
        rs0 += __shfl_xor_sync(0xffffffffu, rs0, 2);
        rs1 += __shfl_xor_sync(0xffffffffu, rs1, 1);
        rs1 += __shfl_xor_sync(0xffffffffu, rs1, 2);
        l0 = l0 * al0 + rs0; l1 = l1 * al1 + rs1;
        m0 = mn0; m1 = mn1;
        #pragma unroll
        for (int j = 0; j < 16; j++) {
            oacc[j][0] *= al0; oacc[j][1] *= al0;
            oacc[j][2] *= al1; oacc[j][3] *= al1;
        }
        __syncwarp();

        // O += P V  (16 rows x 128 d, k=64)
        #pragma unroll
        for (int ko = 0; ko < 64; ko += 8) {
            uint32_t a[4];
            a[0] = fu(Ps[rb + g][ko + tig]);
            a[1] = fu(Ps[rb + g + 8][ko + tig]);
            a[2] = fu(Ps[rb + g][ko + tig + 4]);
            a[3] = fu(Ps[rb + g + 8][ko + tig + 4]);
            #pragma unroll
            for (int j = 0; j < 16; j++) {
                uint32_t bf[2]; int db = j * 8;
                bf[0] = fu(Vs[ko + tig][db + g]);
                bf[1] = fu(Vs[ko + tig + 4][db + g]);
                mma8(oacc[j], a, bf);
            }
        }
    }

    float inv0 = 1.f / l0, inv1 = 1.f / l1;
    int rowg0 = b * NN + q0 + w * 16 + g;
    #pragma unroll
    for (int j = 0; j < 16; j++) {
        int col = j * 8 + 2 * tig;
        float* d0 = &g_o[((size_t)rowg0 * HH + h) * HDD + col];
        d0[0] = oacc[j][0] * inv0; d0[1] = oacc[j][1] * inv0;
        float* d1 = &g_o[((size_t)(rowg0 + 8) * HH + h) * HDD + col];
        d1[0] = oacc[j][2] * inv1; d1[1] = oacc[j][3] * inv1;
    }
}

// ---------------- grouped output projection ----------------
__global__ __launch_bounds__(256, 1) void yh_gemm(const float* __restrict__ Wo) {
    int e = blockIdx.x;
    int cnt = g_cnt[e];
    int m0 = blockIdx.y * 128;
    if (m0 >= cnt) return;
    int n0 = blockIdx.z * 128;
    __shared__ float As[128][AST];
    __shared__ float Bs[16][BST];
    __shared__ int   s_ent[128];
    __shared__ float s_gate[128];
    int tid = threadIdx.x;
    int off = g_off[e];
    if (tid < 128) {
        int ent = (m0 + tid < cnt) ? g_perm[off + m0 + tid] : -1;
        s_ent[tid] = ent;
        s_gate[tid] = (ent >= 0) ? g_gates[ent] : 0.f;
    }
    __syncthreads();
    int w = tid >> 5, lane = tid & 31, g = lane >> 2, tig = lane & 3;
    int wm = w & 3, wn = w >> 2;
    float c[2][8][4];
    #pragma unroll
    for (int i = 0; i < 2; i++) for (int j = 0; j < 8; j++) for (int q = 0; q < 4; q++) c[i][j][q] = 0.f;
    const float* Wb = Wo + (size_t)e * HDD * DD;

    for (int k0 = 0; k0 < HDD; k0 += 16) {
        #pragma unroll
        for (int i = 0; i < 2; i++) {
            int idx = tid * 2 + i; int r = idx >> 2, kq = (idx & 3) * 4;
            int ent = s_ent[r];
            float4 v = make_float4(0.f, 0.f, 0.f, 0.f);
            if (ent >= 0) v = *(const float4*)&g_o[(size_t)ent * HDD + k0 + kq];
            *(float4*)&As[r][kq] = make_float4(to_tf32(v.x), to_tf32(v.y), to_tf32(v.z), to_tf32(v.w));
        }
        #pragma unroll
        for (int i = 0; i < 2; i++) {
            int idx = tid * 2 + i; int kr = idx >> 5, cc = (idx & 31) * 4;
            float4 v = *(const float4*)(Wb + (size_t)(k0 + kr) * DD + n0 + cc);
            *(float4*)&Bs[kr][cc] = make_float4(to_tf32(v.x), to_tf32(v.y), to_tf32(v.z), to_tf32(v.w));
        }
        __syncthreads();
        #pragma unroll
        for (int ko = 0; ko < 16; ko += 8) {
            uint32_t a[2][4], bf[8][2];
            #pragma unroll
            for (int i = 0; i < 2; i++) {
                int rb = wm * 32 + i * 16;
                a[i][0] = fu(As[rb + g][ko + tig]);
                a[i][1] = fu(As[rb + g + 8][ko + tig]);
                a[i][2] = fu(As[rb + g][ko + tig + 4]);
                a[i][3] = fu(As[rb + g + 8][ko + tig + 4]);
            }
            #pragma unroll
            for (int j = 0; j < 8; j++) {
                int cb = wn * 64 + j * 8;
                bf[j][0] = fu(Bs[ko + tig][cb + g]);
                bf[j][1] = fu(Bs[ko + tig + 4][cb + g]);
            }
            #pragma unroll
            for (int i = 0; i < 2; i++)
                #pragma unroll
                for (int j = 0; j < 8; j++) mma8(c[i][j], a[i], bf[j]);
        }
        __syncthreads();
    }
    #pragma unroll
    for (int i = 0; i < 2; i++) {
        #pragma unroll
        for (int half = 0; half < 2; half++) {
            int mi = wm * 32 + i * 16 + g + half * 8;
            int ent = s_ent[mi];
            if (ent >= 0) {
                float gt = s_gate[mi];
                #pragma unroll
                for (int j = 0; j < 8; j++) {
                    int col = n0 + wn * 64 + j * 8 + 2 * tig;
                    g_yh[(size_t)ent * DD + col]     = c[i][j][half * 2 + 0] * gt;
                    g_yh[(size_t)ent * DD + col + 1] = c[i][j][half * 2 + 1] * gt;
                }
            }
        }
    }
}

// ---------------- reduce over heads (vectorized) ----------------
__global__ void reduce_kernel(float4* __restrict__ out) {
    int idx = blockIdx.x * 256 + threadIdx.x;
    if (idx < RR * DD / 4) {
        int row = idx / (DD / 4);
        int c = idx % (DD / 4);
        const float4* yh4 = (const float4*)g_yh;
        float4 s = make_float4(0.f, 0.f, 0.f, 0.f);
        #pragma unroll
        for (int h = 0; h < HH; h++) {
            float4 v = yh4[(size_t)(row * HH + h) * (DD / 4) + c];
            s.x += v.x; s.y += v.y; s.z += v.z; s.w += v.w;
        }
        out[idx] = s;
    }
}

__global__ void aux_kernel(float* __restrict__ out) {
    float sw = 0.f;
    for (int e = 0; e < EE; e++)
        sw += ((float)g_cnt[e] / (float)RR) * (g_pmean[e] / (float)RR);
    float aux = SWITCHLOSS * (float)EE * sw + ZLOSS * (g_zsum / (float)RR);
    out[(size_t)RR * DD] = aux;
}

// ---------------- launch ----------------
extern "C" void kernel_launch(void* const* d_in, const int* in_sizes, int n_in,
                              void* d_out, int out_size) {
    const float* x       = (const float*)d_in[0];
    const int*   task_bh = (const int*)  d_in[1];
    const float* Wg      = (const float*)d_in[2];
    const float* Wq      = (const float*)d_in[3];
    const float* Wo      = (const float*)d_in[4];
    const float* Wkv     = (const float*)d_in[5];
    const float* bkv     = (const float*)d_in[6];
    float* out = (float*)d_out;

    cudaFuncSetAttribute(attn_kernel, cudaFuncAttributeMaxDynamicSharedMemorySize, ATTN_SMEM);

    init_kernel<<<1, 64>>>();
    gating_kernel<<<RR / 8, 256>>>(x, task_bh, Wg);
    scan_kernel<<<1, 1>>>();
    scatter_kernel<<<ENTN / 256, 256>>>();
    kv_gemm<<<dim3(RR / 128, 2), 256>>>(x, Wkv, bkv);
    q_gemm<<<dim3(EE, ENTN / 128), 256>>>(x, Wq);
    attn_kernel<<<dim3(NN / 128, HH, BB), 256, ATTN_SMEM>>>();
    yh_gemm<<<dim3(EE, ENTN / 128, DD / 128), 256>>>(Wo);
    reduce_kernel<<<(RR * DD / 4) / 256, 256>>>((float4*)out);
    aux_kernel<<<1, 1>>>(out);
}